// round 15
// baseline (speedup 1.0000x reference)
#include <cuda_runtime.h>
#include <cuda_fp16.h>

// Shapes fixed by the dataset
#define Cc 20
#define HW (512 * 1024)          // 2^19
#define NPIX (4 * HW)            // 2097152
#define NCLS 19                  // classes 1..19 (label 0 == ignore)
#define NBINS 256
#define BIN_SCALE 256.0f
#define INV_BINS (1.0f / 256.0f)

#define NW 5                     // packed words per pixel (w0 byte0 = label)
#define P_THREADS 512
#define P_OCC 3                  // 1536 thr/SM, 42-reg cap (proven no-spill)
#define P_BLOCKS (P_OCC * 148)   // 444

// Device scratch (zero-initialized at load; reset in-kernel each replay)
// SoA: word k of pixel p at g_binw[k*NPIX + p] -> fully coalesced.
__device__ unsigned int g_binw[(size_t)NW * NPIX];   // 40 MB
__device__ unsigned long long g_hist[NCLS * NBINS];  // packed: fg<<32 | count
__device__ float g_accum[2];                         // {sum losses, #present}
__device__ unsigned int g_done;

// ---------------------------------------------------------------------------
// Pass 1 (single logits read): softmax; fg entries -> block-private smem hist;
// 19 bg bin bytes packed via f16 SIMD (HFMA2+HMIN2 -> byte0 trick -> PRMT)
// and streamed out SoA. No maxpc tracking: pass 2 derives the per-class
// threshold from the fg histogram (T_c = min fg bin - 1), which is
// equal-or-more-inclusive than the old maxpc formula -> still an exact filter.
__global__ void __launch_bounds__(P_THREADS, P_OCC)
pass1_kernel(const float* __restrict__ logits, const int* __restrict__ labels) {
    __shared__ unsigned int s_fg[NCLS * NBINS];
    const int tid = threadIdx.x;
    for (int i = tid; i < NCLS * NBINS; i += P_THREADS) s_fg[i] = 0u;
    __syncthreads();

    const __half2 c1024 = __floats2half2_rn(1024.0f, 1024.0f);
    const __half2 c1279 = __floats2half2_rn(1279.0f, 1279.0f);

    for (int p = blockIdx.x * P_THREADS + tid; p < NPIX; p += P_BLOCKS * P_THREADS) {
        const int lab = labels[p];
        if (lab == 0) continue;              // never written -> words stay 0
        const int b = p >> 19;
        const int hw = p & (HW - 1);
        const float* base = logits + (size_t)b * (Cc * HW) + hw;

        __half2 vh[Cc / 2];                  // f16 value cache
        float s = 0.0f, vl = 0.0f;
#pragma unroll
        for (int c = 0; c < Cc; c += 2) {
            const float e0 = __expf(base[(size_t)c * HW]);
            const float e1 = __expf(base[(size_t)(c + 1) * HW]);
            s += e0 + e1;
            if (c == lab) vl = e0;
            if (c + 1 == lab) vl = e1;
            vh[c / 2] = __floats2half2_rn(e0, e1);
        }
        const float inv256 = BIN_SCALE / s;

        // fg entry: exact f32 floor bin; always counted
        {
            int bin = (int)(BIN_SCALE - vl * inv256);
            bin = min(max(bin, 0), NBINS - 1);
            atomicAdd(&s_fg[(lab - 1) * NBINS + bin], 1u);
        }

        // SIMD pack: v = min(round(f)+1024, 1279); half bits = 0x64xx | bin,
        // so byte0 of each half is the bin byte. PRMT gathers 4 bins/word.
        const __half2 cinv = __float2half2_rn(inv256);
        unsigned int hb[Cc / 2];
#pragma unroll
        for (int k = 0; k < Cc / 2; k++) {
            const __half2 a = __hmin2(__hfma2(vh[k], cinv, c1024), c1279);
            hb[k] = *(const unsigned int*)&a;
        }
        unsigned int w[NW];
#pragma unroll
        for (int k = 0; k < NW; k++)
            w[k] = __byte_perm(hb[2 * k], hb[2 * k + 1], 0x6420);
        w[0] = __byte_perm(w[0], (unsigned int)lab, 0x3214);  // byte0 <- label
        // (fg class's own byte keeps its prob-bin garbage; pass2 masks it out)

#pragma unroll
        for (int k = 0; k < NW; k++)          // SoA coalesced STG x5
            g_binw[(size_t)k * NPIX + p] = w[k];
    }
    __syncthreads();

    // Flush fg histogram (contributes to both cnt and fg fields)
    for (int i = tid; i < NCLS * NBINS; i += P_THREADS) {
        const unsigned int n = s_fg[i];
        if (n) atomicAdd(&g_hist[i], ((unsigned long long)n << 32) | n);
    }
}

// ---------------------------------------------------------------------------
// Pass 2: derive T_c = max(min fg bin - 1, 0) from g_hist's fg fields (final
// after the pass-1 kernel boundary); then SIMD-filter the packed bin bytes.
// byte >= T_c with the -1 margin + f16 round-vs-floor (<=1 bin) perturbation
// can only over-include; over-included entries sit where jaccard==1 on both
// sides -> contribute exactly 0. Survivor visits via movemask + ffs loop.
__global__ void __launch_bounds__(P_THREADS, P_OCC)
pass2_kernel() {
    __shared__ unsigned int s_cnt[NCLS * NBINS];
    __shared__ int sMin[NCLS];
    __shared__ unsigned int sTw[NW];

    const int tid = threadIdx.x;
    for (int i = tid; i < NCLS * NBINS; i += P_THREADS) s_cnt[i] = 0u;
    if (tid < NCLS) sMin[tid] = 256;
    __syncthreads();
    for (int i = tid; i < NCLS * NBINS; i += P_THREADS)
        if ((unsigned int)(g_hist[i] >> 32)) atomicMin(&sMin[i >> 8], i & 255);
    __syncthreads();
    if (tid < NW) {
        unsigned int w = 0u;
#pragma unroll
        for (int j = 0; j < 4; j++) {
            const int c = tid * 4 + j;
            unsigned int tb = 255u;          // byte0 (label) / no-fg classes
            if (c >= 1 && c < Cc) {
                const int T = sMin[c - 1] - 1;               // 255 if no fg
                tb = (unsigned int)min(max(T, 0), 255);
            }
            w |= tb << (8 * j);
        }
        sTw[tid] = w;
    }
    __syncthreads();

    for (int p = blockIdx.x * P_THREADS + tid; p < NPIX; p += P_BLOCKS * P_THREADS) {
        unsigned int w[NW];
#pragma unroll
        for (int k = 0; k < NW; k++)          // SoA coalesced LDG x5
            w[k] = g_binw[(size_t)k * NPIX + p];
        const int lab = (int)(w[0] & 255u);
        if (lab == 0) continue;               // ignored pixel
        const int labw = lab >> 2;
        const unsigned int labclr = ~(1u << ((lab & 3) * 8));

#pragma unroll
        for (int k = 0; k < NW; k++) {
            unsigned int mm = __vcmpgeu4(w[k], sTw[k]) & 0x01010101u;
            mm &= (k == labw) ? labclr : 0xFFFFFFFFu;   // exclude fg byte
            while (mm) {                       // visits only survivors (~1.3/px)
                const int j = (__ffs(mm) - 1) >> 3;
                const unsigned int bin = (w[k] >> (8 * j)) & 255u;
                atomicAdd(&s_cnt[(k * 4 + j - 1) * NBINS + bin], 1u);
                mm &= mm - 1;
            }
        }
    }
    __syncthreads();

    for (int i = tid; i < NCLS * NBINS; i += P_THREADS) {
        const unsigned int n = s_cnt[i];
        if (n) atomicAdd(&g_hist[i], (unsigned long long)n);
    }
}

// ---------------------------------------------------------------------------
__device__ __forceinline__ unsigned long long warp_incl_scan_u64(unsigned long long x) {
#pragma unroll
    for (int d = 1; d < 32; d <<= 1) {
        unsigned long long y = __shfl_up_sync(0xffffffffu, x, d);
        if ((threadIdx.x & 31) >= d) x += y;
    }
    return x;
}

// One block per class, one thread per bin (descending error). Tie-group ->
// e * (J(after) - J(before)). Last finishing block emits the final scalar.
__global__ void __launch_bounds__(NBINS) scan_kernel(float* __restrict__ out) {
    __shared__ unsigned long long wsum[8];
    __shared__ unsigned long long s_total;
    __shared__ float red[8];

    const int cls = blockIdx.x;
    const int t = threadIdx.x;
    const int lane = t & 31;
    const int warp = t >> 5;
    const int bin = (NBINS - 1) - t;          // thread 0 = highest error bin
    const int idx = cls * NBINS + bin;

    const unsigned long long v = g_hist[idx];
    g_hist[idx] = 0ull;                       // reset for next replay

    unsigned long long sc = warp_incl_scan_u64(v);
    if (lane == 31) wsum[warp] = sc;
    __syncthreads();
    if (warp == 0) {
        unsigned long long w = (lane < 8) ? wsum[lane] : 0ull;
#pragma unroll
        for (int d = 1; d < 8; d <<= 1) {
            unsigned long long y = __shfl_up_sync(0xffffffffu, w, d);
            if (lane >= d) w += y;
        }
        if (lane < 8) wsum[lane] = w;
    }
    __syncthreads();
    const unsigned long long incl = sc + (warp > 0 ? wsum[warp - 1] : 0ull);
    if (t == NBINS - 1) s_total = incl;
    __syncthreads();

    const unsigned int gts = (unsigned int)(s_total >> 32);
    const unsigned int ct = (unsigned int)v;
    float contrib = 0.0f;
    if (ct && gts) {
        const float fgts = (float)gts;
        const unsigned int ct_a = (unsigned int)incl;
        const unsigned int cf_a = (unsigned int)(incl >> 32);
        const unsigned int ct_b = ct_a - ct;
        const unsigned int cf_b = cf_a - (unsigned int)(v >> 32);
        const float Ja = 1.0f - (fgts - (float)cf_a) / (fgts + (float)ct_a - (float)cf_a);
        const float Jb = 1.0f - (fgts - (float)cf_b) / (fgts + (float)ct_b - (float)cf_b);
        const float e = ((float)bin + 0.5f) * INV_BINS;
        contrib = e * (Ja - Jb);
    }

#pragma unroll
    for (int d = 16; d; d >>= 1) contrib += __shfl_down_sync(0xffffffffu, contrib, d);
    if (lane == 0) red[warp] = contrib;
    __syncthreads();
    if (warp == 0 && lane == 0) {
        float x = 0.0f;
#pragma unroll
        for (int i = 0; i < 8; i++) x += red[i];
        if (gts) {
            atomicAdd(&g_accum[0], x);
            atomicAdd(&g_accum[1], 1.0f);
        }
        __threadfence();
        const unsigned int prev = atomicAdd(&g_done, 1u);
        if (prev == NCLS - 1) {               // last class block: fused final
            const float num = atomicAdd(&g_accum[0], 0.0f);
            const float den = atomicAdd(&g_accum[1], 0.0f);
            out[0] = num / fmaxf(den, 1.0f);
            g_accum[0] = 0.0f;
            g_accum[1] = 0.0f;
            g_done = 0u;
        }
    }
}

// ---------------------------------------------------------------------------
extern "C" void kernel_launch(void* const* d_in, const int* in_sizes, int n_in,
                              void* d_out, int out_size) {
    const float* logits = (const float*)d_in[0];
    const int* labels = (const int*)d_in[1];
    float* out = (float*)d_out;

    static int configured = 0;
    if (!configured) {
        cudaFuncSetAttribute(pass1_kernel,
                             cudaFuncAttributePreferredSharedMemoryCarveout,
                             cudaSharedmemCarveoutMaxShared);
        cudaFuncSetAttribute(pass2_kernel,
                             cudaFuncAttributePreferredSharedMemoryCarveout,
                             cudaSharedmemCarveoutMaxShared);
        configured = 1;
    }

    pass1_kernel<<<P_BLOCKS, P_THREADS>>>(logits, labels);
    pass2_kernel<<<P_BLOCKS, P_THREADS>>>();
    scan_kernel<<<NCLS, NBINS>>>(out);
}

// round 16
// speedup vs baseline: 1.0284x; 1.0284x over previous
#include <cuda_runtime.h>
#include <cuda_fp16.h>

// Shapes fixed by the dataset
#define Cc 20
#define HW (512 * 1024)          // 2^19
#define NPIX (4 * HW)            // 2097152
#define NCLS 19                  // classes 1..19 (label 0 == ignore)
#define NBINS 256
#define BIN_SCALE 256.0f
#define INV_BINS (1.0f / 256.0f)

#define NW 5                     // packed words per pixel (w0 byte0 = label)
#define P_THREADS 512
#define P_OCC 3                  // 1536 thr/SM, 42-reg cap (proven no-spill)
#define P_BLOCKS (P_OCC * 148)   // 444

// Device scratch (zero-initialized at load; reset in-kernel each replay)
// SoA: word k of pixel p at g_binw[k*NPIX + p] -> coalesced, uint4-friendly.
__device__ unsigned int g_binw[(size_t)NW * NPIX];   // 40 MB
__device__ unsigned long long g_hist[NCLS * NBINS];  // packed: fg<<32 | count
__device__ float g_accum[2];                         // {sum losses, #present}
__device__ unsigned int g_done;

// ---------------------------------------------------------------------------
// Pass 1 (single logits read): softmax; fg entries -> block-private smem hist;
// 19 bg bin bytes packed via f16 SIMD (HFMA2+HMIN2 byte0 trick -> PRMT),
// streamed out SoA. Pass 2 derives thresholds from the fg histogram.
__global__ void __launch_bounds__(P_THREADS, P_OCC)
pass1_kernel(const float* __restrict__ logits, const int* __restrict__ labels) {
    __shared__ unsigned int s_fg[NCLS * NBINS];
    const int tid = threadIdx.x;
    for (int i = tid; i < NCLS * NBINS; i += P_THREADS) s_fg[i] = 0u;
    __syncthreads();

    const __half2 c1024 = __floats2half2_rn(1024.0f, 1024.0f);
    const __half2 c1279 = __floats2half2_rn(1279.0f, 1279.0f);

    for (int p = blockIdx.x * P_THREADS + tid; p < NPIX; p += P_BLOCKS * P_THREADS) {
        const int lab = labels[p];
        if (lab == 0) continue;              // never written -> words stay 0
        const int b = p >> 19;
        const int hw = p & (HW - 1);
        const float* base = logits + (size_t)b * (Cc * HW) + hw;

        __half2 vh[Cc / 2];                  // f16 value cache
        float s = 0.0f, vl = 0.0f;
#pragma unroll
        for (int c = 0; c < Cc; c += 2) {
            const float e0 = __expf(base[(size_t)c * HW]);
            const float e1 = __expf(base[(size_t)(c + 1) * HW]);
            s += e0 + e1;
            if (c == lab) vl = e0;
            if (c + 1 == lab) vl = e1;
            vh[c / 2] = __floats2half2_rn(e0, e1);
        }
        const float inv256 = BIN_SCALE / s;

        // fg entry: exact f32 floor bin; always counted
        {
            int bin = (int)(BIN_SCALE - vl * inv256);
            bin = min(max(bin, 0), NBINS - 1);
            atomicAdd(&s_fg[(lab - 1) * NBINS + bin], 1u);
        }

        // SIMD pack: v = min(round(f)+1024, 1279); half bits = 0x64xx | bin,
        // so byte0 of each half is the bin byte. PRMT gathers 4 bins/word.
        const __half2 cinv = __float2half2_rn(inv256);
        unsigned int hb[Cc / 2];
#pragma unroll
        for (int k = 0; k < Cc / 2; k++) {
            const __half2 a = __hmin2(__hfma2(vh[k], cinv, c1024), c1279);
            hb[k] = *(const unsigned int*)&a;
        }
        unsigned int w[NW];
#pragma unroll
        for (int k = 0; k < NW; k++)
            w[k] = __byte_perm(hb[2 * k], hb[2 * k + 1], 0x6420);
        w[0] = __byte_perm(w[0], (unsigned int)lab, 0x3214);  // byte0 <- label

#pragma unroll
        for (int k = 0; k < NW; k++)          // SoA coalesced STG x5
            g_binw[(size_t)k * NPIX + p] = w[k];
    }
    __syncthreads();

    // Flush fg histogram (contributes to both cnt and fg fields)
    for (int i = tid; i < NCLS * NBINS; i += P_THREADS) {
        const unsigned int n = s_fg[i];
        if (n) atomicAdd(&g_hist[i], ((unsigned long long)n << 32) | n);
    }
}

// ---------------------------------------------------------------------------
// Pass 2, quad-pixel vectorized: each thread handles 4 consecutive pixels via
// five LDG.128 (one per SoA word-plane). Thresholds T_c = max(min fg bin-1,0)
// derived from g_hist's fg fields. Over-inclusion from the -1 margin and f16
// rounding lands where jaccard==1 on both sides -> contributes exactly 0.
__global__ void __launch_bounds__(P_THREADS, P_OCC)
pass2_kernel() {
    __shared__ unsigned int s_cnt[NCLS * NBINS];
    __shared__ int sMin[NCLS];
    __shared__ unsigned int sTw[NW];

    const int tid = threadIdx.x;
    for (int i = tid; i < NCLS * NBINS; i += P_THREADS) s_cnt[i] = 0u;
    if (tid < NCLS) sMin[tid] = 256;
    __syncthreads();
    for (int i = tid; i < NCLS * NBINS; i += P_THREADS)
        if ((unsigned int)(g_hist[i] >> 32)) atomicMin(&sMin[i >> 8], i & 255);
    __syncthreads();
    if (tid < NW) {
        unsigned int w = 0u;
#pragma unroll
        for (int j = 0; j < 4; j++) {
            const int c = tid * 4 + j;
            unsigned int tb = 255u;          // byte0 (label) / no-fg classes
            if (c >= 1 && c < Cc) {
                const int T = sMin[c - 1] - 1;               // 255 if no fg
                tb = (unsigned int)min(max(T, 0), 255);
            }
            w |= tb << (8 * j);
        }
        sTw[tid] = w;
    }
    __syncthreads();

    const int nquad = NPIX / 4;
    for (int t = blockIdx.x * P_THREADS + tid; t < nquad; t += P_BLOCKS * P_THREADS) {
        unsigned int q[NW][4];
#pragma unroll
        for (int k = 0; k < NW; k++) {        // LDG.128 x5 (SoA planes)
            const uint4 v = ((const uint4*)(g_binw + (size_t)k * NPIX))[t];
            q[k][0] = v.x; q[k][1] = v.y; q[k][2] = v.z; q[k][3] = v.w;
        }
#pragma unroll
        for (int j = 0; j < 4; j++) {         // 4 pixels in the quad
            const int lab = (int)(q[0][j] & 255u);
            if (lab == 0) continue;           // ignored pixel
            const int labw = lab >> 2;
            const unsigned int labclr = ~(1u << ((lab & 3) * 8));
#pragma unroll
            for (int k = 0; k < NW; k++) {
                const unsigned int w = q[k][j];
                unsigned int mm = __vcmpgeu4(w, sTw[k]) & 0x01010101u;
                mm &= (k == labw) ? labclr : 0xFFFFFFFFu;   // exclude fg byte
                while (mm) {                  // visits only survivors (~1.3/px)
                    const int jj = (__ffs(mm) - 1) >> 3;
                    const unsigned int bin = (w >> (8 * jj)) & 255u;
                    atomicAdd(&s_cnt[(k * 4 + jj - 1) * NBINS + bin], 1u);
                    mm &= mm - 1;
                }
            }
        }
    }
    __syncthreads();

    for (int i = tid; i < NCLS * NBINS; i += P_THREADS) {
        const unsigned int n = s_cnt[i];
        if (n) atomicAdd(&g_hist[i], (unsigned long long)n);
    }
}

// ---------------------------------------------------------------------------
__device__ __forceinline__ unsigned long long warp_incl_scan_u64(unsigned long long x) {
#pragma unroll
    for (int d = 1; d < 32; d <<= 1) {
        unsigned long long y = __shfl_up_sync(0xffffffffu, x, d);
        if ((threadIdx.x & 31) >= d) x += y;
    }
    return x;
}

// One block per class, one thread per bin (descending error). Tie-group ->
// e * (J(after) - J(before)). Last finishing block emits the final scalar.
__global__ void __launch_bounds__(NBINS) scan_kernel(float* __restrict__ out) {
    __shared__ unsigned long long wsum[8];
    __shared__ unsigned long long s_total;
    __shared__ float red[8];

    const int cls = blockIdx.x;
    const int t = threadIdx.x;
    const int lane = t & 31;
    const int warp = t >> 5;
    const int bin = (NBINS - 1) - t;          // thread 0 = highest error bin
    const int idx = cls * NBINS + bin;

    const unsigned long long v = g_hist[idx];
    g_hist[idx] = 0ull;                       // reset for next replay

    unsigned long long sc = warp_incl_scan_u64(v);
    if (lane == 31) wsum[warp] = sc;
    __syncthreads();
    if (warp == 0) {
        unsigned long long w = (lane < 8) ? wsum[lane] : 0ull;
#pragma unroll
        for (int d = 1; d < 8; d <<= 1) {
            unsigned long long y = __shfl_up_sync(0xffffffffu, w, d);
            if (lane >= d) w += y;
        }
        if (lane < 8) wsum[lane] = w;
    }
    __syncthreads();
    const unsigned long long incl = sc + (warp > 0 ? wsum[warp - 1] : 0ull);
    if (t == NBINS - 1) s_total = incl;
    __syncthreads();

    const unsigned int gts = (unsigned int)(s_total >> 32);
    const unsigned int ct = (unsigned int)v;
    float contrib = 0.0f;
    if (ct && gts) {
        const float fgts = (float)gts;
        const unsigned int ct_a = (unsigned int)incl;
        const unsigned int cf_a = (unsigned int)(incl >> 32);
        const unsigned int ct_b = ct_a - ct;
        const unsigned int cf_b = cf_a - (unsigned int)(v >> 32);
        const float Ja = 1.0f - (fgts - (float)cf_a) / (fgts + (float)ct_a - (float)cf_a);
        const float Jb = 1.0f - (fgts - (float)cf_b) / (fgts + (float)ct_b - (float)cf_b);
        const float e = ((float)bin + 0.5f) * INV_BINS;
        contrib = e * (Ja - Jb);
    }

#pragma unroll
    for (int d = 16; d; d >>= 1) contrib += __shfl_down_sync(0xffffffffu, contrib, d);
    if (lane == 0) red[warp] = contrib;
    __syncthreads();
    if (warp == 0 && lane == 0) {
        float x = 0.0f;
#pragma unroll
        for (int i = 0; i < 8; i++) x += red[i];
        if (gts) {
            atomicAdd(&g_accum[0], x);
            atomicAdd(&g_accum[1], 1.0f);
        }
        __threadfence();
        const unsigned int prev = atomicAdd(&g_done, 1u);
        if (prev == NCLS - 1) {               // last class block: fused final
            const float num = atomicAdd(&g_accum[0], 0.0f);
            const float den = atomicAdd(&g_accum[1], 0.0f);
            out[0] = num / fmaxf(den, 1.0f);
            g_accum[0] = 0.0f;
            g_accum[1] = 0.0f;
            g_done = 0u;
        }
    }
}

// ---------------------------------------------------------------------------
extern "C" void kernel_launch(void* const* d_in, const int* in_sizes, int n_in,
                              void* d_out, int out_size) {
    const float* logits = (const float*)d_in[0];
    const int* labels = (const int*)d_in[1];
    float* out = (float*)d_out;

    static int configured = 0;
    if (!configured) {
        cudaFuncSetAttribute(pass1_kernel,
                             cudaFuncAttributePreferredSharedMemoryCarveout,
                             cudaSharedmemCarveoutMaxShared);
        cudaFuncSetAttribute(pass2_kernel,
                             cudaFuncAttributePreferredSharedMemoryCarveout,
                             cudaSharedmemCarveoutMaxShared);
        configured = 1;
    }

    pass1_kernel<<<P_BLOCKS, P_THREADS>>>(logits, labels);
    pass2_kernel<<<P_BLOCKS, P_THREADS>>>();
    scan_kernel<<<NCLS, NBINS>>>(out);
}